// round 16
// baseline (speedup 1.0000x reference)
#include <cuda_runtime.h>
#include <cuda_bf16.h>
#include <cuda_fp16.h>
#include <math.h>
#include <stdint.h>
#include <string.h>

// ----------------------------------------------------------------------------
// Problem constants
// ----------------------------------------------------------------------------
#define T_TOK 2048
#define D_MODEL 2048
#define N_Q 16
#define N_KV 4
#define HEAD 128
#define QH (N_Q*HEAD)      // 2048
#define KVH (N_KV*HEAD)    // 512
#define N_EXP 16
#define F_FF 1024
#define TOPK 4
#define SLOTS (T_TOK*TOPK) // 8192
#define EPS 1e-6f

// ----------------------------------------------------------------------------
// Scratch (device globals; no dynamic allocation allowed)
// ----------------------------------------------------------------------------
__device__ __half g_hnorm_h[T_TOK*D_MODEL];   // reused as Qh after QKV GEMM
__device__ float  g_q[T_TOK*QH];
__device__ float  g_k[T_TOK*KVH];
__device__ float  g_v[T_TOK*KVH];
__device__ __half g_kh[T_TOK*KVH];
__device__ __half g_vT[(size_t)KVH*T_TOK];    // [kvh*128+d][t] fp16
__device__ __half g_attn_h[T_TOK*QH];
__device__ float  g_resid2[T_TOK*D_MODEL];
__device__ float  g_h2[T_TOK*D_MODEL];
__device__ __half g_h2h[T_TOK*D_MODEL];
__device__ float  g_topw[SLOTS];
__device__ int    g_topidx[SLOTS];
__device__ int    g_cnt[N_EXP];
__device__ int    g_off[N_EXP+1];
__device__ int    g_cursor[N_EXP];
__device__ int    g_tokperm[SLOTS];
__device__ int    g_slotrow[SLOTS];
__device__ __half g_gated_h[(size_t)SLOTS*F_FF];
__device__ __half g_downo_h[(size_t)SLOTS*D_MODEL];
// fp16 transposed weights [N][K]
__device__ __half g_qwT[(size_t)2048*2048];
__device__ __half g_kwT[(size_t)512*2048];
__device__ __half g_vwT[(size_t)512*2048];
__device__ __half g_owT[(size_t)2048*2048];
__device__ __half g_guwT[(size_t)N_EXP*2048*2048];
__device__ __half g_dwwT[(size_t)N_EXP*2048*1024];

// ----------------------------------------------------------------------------
// helpers (baseline PTX; compute_103-safe, no 'a'-features)
// ----------------------------------------------------------------------------
__device__ __forceinline__ uint32_t smem_u32(const void* p) {
    uint32_t a;
    asm("{ .reg .u64 t; cvta.to.shared.u64 t, %1; cvt.u32.u64 %0, t; }"
        : "=r"(a) : "l"(p));
    return a;
}
__device__ __forceinline__ void cp16(uint32_t dst, const void* src) {
    asm volatile("cp.async.cg.shared.global [%0], [%1], 16;" :: "r"(dst), "l"(src));
}
__device__ __forceinline__ uint32_t pkh(float lo, float hi) {
    __half2 h = __floats2half2_rn(lo, hi);
    uint32_t u; memcpy(&u, &h, 4); return u;
}

#define MMA_F16(cc, aa, bb) \
    asm volatile("mma.sync.aligned.m16n8k16.row.col.f32.f16.f16.f32 " \
        "{%0,%1,%2,%3}, {%4,%5,%6,%7}, {%8,%9}, {%0,%1,%2,%3};" \
        : "+f"(cc[0]), "+f"(cc[1]), "+f"(cc[2]), "+f"(cc[3]) \
        : "r"(aa[0]), "r"(aa[1]), "r"(aa[2]), "r"(aa[3]), "r"(bb[0]), "r"(bb[1]))

// ----------------------------------------------------------------------------
// fp16 tensor-core GEMM: block 128x128x32(k halfs), 256 thr, 8 warps,
// 3-stage cp.async.  Stage = 20480B; 3 stages -> 2 CTA/SM.
// ----------------------------------------------------------------------------
#define HSTG_BYTES 20480u
#define HSTG_U32   5120
#define HGEMM_SMEM (3*20480)

#define H_ISSUE(S, IT) do {                                                    \
    const int k0_ = (IT)*32;                                                   \
    uint32_t sb_ = smemU + (uint32_t)(S)*HSTG_BYTES;                           \
    cp16(sb_ + aoff[0], arp[0] + k0_);                                         \
    cp16(sb_ + aoff[1], arp[1] + k0_);                                         \
    cp16(sb_ + boff[0], brp[0] + k0_);                                         \
    cp16(sb_ + boff[1], brp[1] + k0_);                                         \
    asm volatile("cp.async.commit_group;" ::: "memory");                       \
} while(0)

#define H_COMPUTE(S) do {                                                      \
    const uint32_t* as_ = smu + (S)*HSTG_U32;                                  \
    const uint32_t* bs_ = as_ + 2560;                                          \
    _Pragma("unroll")                                                          \
    for (int ks_ = 0; ks_ < 2; ks_++) {                                        \
        const int kk0 = ks_*8;                                                 \
        uint32_t af[4][4], bf[4][2];                                           \
        _Pragma("unroll")                                                      \
        for (int mt_=0; mt_<4; mt_++) {                                        \
            int r_ = wm + mt_*16 + rA;                                         \
            af[mt_][0] = as_[r_*20     + kk0 + kq];                            \
            af[mt_][1] = as_[(r_+8)*20 + kk0 + kq];                            \
            af[mt_][2] = as_[r_*20     + kk0 + 4 + kq];                        \
            af[mt_][3] = as_[(r_+8)*20 + kk0 + 4 + kq];                        \
        }                                                                      \
        _Pragma("unroll")                                                      \
        for (int nt_=0; nt_<4; nt_++) {                                        \
            int n_ = wn + nt_*8 + rA;                                          \
            bf[nt_][0] = bs_[n_*20 + kk0 + kq];                                \
            bf[nt_][1] = bs_[n_*20 + kk0 + 4 + kq];                            \
        }                                                                      \
        _Pragma("unroll")                                                      \
        for (int mt_=0; mt_<4; mt_++)                                          \
            _Pragma("unroll")                                                  \
            for (int nt_=0; nt_<4; nt_++)                                      \
                MMA_F16(c[mt_][nt_], af[mt_], bf[nt_]);                        \
    }                                                                          \
} while(0)

#define H_BODY(S) do {                                                         \
    asm volatile("cp.async.wait_group 1;" ::: "memory");                       \
    __syncthreads();                                                           \
    if (itv + 2 < nIter) { H_ISSUE(((S)+2)%3, itv+2); }                        \
    else { asm volatile("cp.async.commit_group;" ::: "memory"); }              \
    H_COMPUTE(S);                                                              \
    itv++;                                                                     \
} while(0)

#define H_PIPELINE()                                                           \
    const int nIter = K / 32;                                                  \
    H_ISSUE(0, 0);                                                             \
    H_ISSUE(1, 1);                                                             \
    int itv = 0;                                                               \
    while (itv + 3 <= nIter) { H_BODY(0); H_BODY(1); H_BODY(2); }              \
    if (itv < nIter) { H_BODY(0); }                                            \
    if (itv < nIter) { H_BODY(1); }

// MODE 0: plain (+Cadd, f32 out).
// MODE 1: MoE gate_up, N-tile = 64 gate cols + 64 up cols, fused silu -> half.
// MODE 2: MoE down -> half out.
template<int MODE, int K>
__global__ __launch_bounds__(256, 2)
void hgemm(const __half* __restrict__ A, const __half* __restrict__ Bt,
           const float* __restrict__ Cadd, void* __restrict__ Cv_, int ldc)
{
    extern __shared__ uint32_t smu[];
    const uint32_t smemU = smem_u32(smu);

    const int tid  = threadIdx.x;
    const int lane = tid & 31;
    const int w    = tid >> 5;
    const int wm   = (w & 1) * 64;
    const int wnh  = w >> 1;
    const int wn   = wnh * 32;
    const int rA   = lane >> 2;
    const int kq   = lane & 3;
    const int bn   = blockIdx.x * 128;     // MODE 0/2
    const int bn64 = blockIdx.x * 64;      // MODE 1 gate-col base
    const int m0   = blockIdx.y * 128;

    int cnt_rows = 128;
    int base = 0;
    size_t cBase;
    const __half* Bsrc = Bt;
    if (MODE == 0) {
        cBase = (size_t)m0 * ldc;
    } else {
        const int e = blockIdx.z;
        const int cnt = g_cnt[e];
        if (m0 >= cnt) return;
        base = g_off[e];
        cnt_rows = min(128, cnt - m0);
        Bsrc = Bt + (size_t)e * 2048u * (size_t)K;
        cBase = (size_t)(base + m0) * ldc;
    }

    const __half* arp[2];
    const __half* brp[2];
    uint32_t aoff[2], boff[2];
    #pragma unroll
    for (int i = 0; i < 2; i++) {
        int idx = tid + i * 256;
        int r = idx >> 2, cc = idx & 3;
        int rl = min(r, cnt_rows - 1);
        size_t gr;
        if (MODE == 0)      gr = (size_t)(m0 + r);
        else if (MODE == 1) gr = (size_t)g_tokperm[base + m0 + rl];
        else                gr = (size_t)(base + m0 + rl);
        arp[i]  = A + gr * (size_t)K + cc * 8;
        aoff[i] = 80u * (uint32_t)r + 16u * (uint32_t)cc;
        int bcol;
        if (MODE == 1) bcol = (r < 64) ? (bn64 + r) : (1024 + bn64 + r - 64);
        else           bcol = bn + r;
        brp[i]  = Bsrc + (size_t)bcol * K + cc * 8;
        boff[i] = 10240u + 80u * (uint32_t)r + 16u * (uint32_t)cc;
    }

    float c[4][4][4] = {};
    H_PIPELINE();

    if (MODE == 1) {
        // fused silu(gate)*up epilogue; gate accums cross warps via stage smem
        __syncthreads();
        float* Gbuf = (float*)smu;             // [128][68] f32
        if (wnh < 2) {
            #pragma unroll
            for (int mt = 0; mt < 4; mt++)
                #pragma unroll
                for (int h = 0; h < 2; h++) {
                    int r = wm + mt * 16 + rA + h * 8;
                    #pragma unroll
                    for (int nt = 0; nt < 4; nt++) {
                        int cg = wn + nt * 8 + (kq << 1);
                        Gbuf[r * 68 + cg]     = c[mt][nt][h * 2 + 0];
                        Gbuf[r * 68 + cg + 1] = c[mt][nt][h * 2 + 1];
                    }
                }
        }
        __syncthreads();
        if (wnh >= 2) {
            __half* C = (__half*)Cv_;
            #pragma unroll
            for (int mt = 0; mt < 4; mt++)
                #pragma unroll
                for (int h = 0; h < 2; h++) {
                    int r = wm + mt * 16 + rA + h * 8;
                    if (r < cnt_rows) {
                        __half* dst = C + cBase + (size_t)r * ldc + bn64;
                        #pragma unroll
                        for (int nt = 0; nt < 4; nt++) {
                            int cu = (wn - 64) + nt * 8 + (kq << 1);
                            float g0 = Gbuf[r * 68 + cu];
                            float g1 = Gbuf[r * 68 + cu + 1];
                            float u0 = c[mt][nt][h * 2 + 0];
                            float u1 = c[mt][nt][h * 2 + 1];
                            float o0 = u0 * (g0 / (1.f + __expf(-g0)));
                            float o1 = u1 * (g1 / (1.f + __expf(-g1)));
                            *(uint32_t*)(dst + cu) = pkh(o0, o1);
                        }
                    }
                }
        }
        return;
    }

    if (MODE == 2) {
        __half* C = (__half*)Cv_;
        #pragma unroll
        for (int mt = 0; mt < 4; mt++) {
            #pragma unroll
            for (int h = 0; h < 2; h++) {
                int r = wm + mt * 16 + rA + h * 8;
                if (r < cnt_rows) {
                    __half* dst = C + cBase + (size_t)r * ldc + bn;
                    #pragma unroll
                    for (int nt = 0; nt < 4; nt++) {
                        int col = wn + nt * 8 + (kq << 1);
                        *(uint32_t*)(dst + col) =
                            pkh(c[mt][nt][h*2+0], c[mt][nt][h*2+1]);
                    }
                }
            }
        }
        return;
    }

    float* C = (float*)Cv_;
    #pragma unroll
    for (int mt = 0; mt < 4; mt++) {
        #pragma unroll
        for (int h = 0; h < 2; h++) {
            int r = wm + mt * 16 + rA + h * 8;
            if (r < cnt_rows) {
                float* dst = C + cBase + (size_t)r * ldc + bn;
                const float* ad = Cadd ? (Cadd + cBase + (size_t)r * ldc + bn)
                                       : (const float*)0;
                #pragma unroll
                for (int nt = 0; nt < 4; nt++) {
                    int col = wn + nt * 8 + (kq << 1);
                    float v0 = c[mt][nt][h * 2 + 0];
                    float v1 = c[mt][nt][h * 2 + 1];
                    if (ad) { v0 += ad[col]; v1 += ad[col + 1]; }
                    dst[col]     = v0;
                    dst[col + 1] = v1;
                }
            }
        }
    }
}

// ----------------------------------------------------------------------------
// Fused QKV fp16 GEMM
// ----------------------------------------------------------------------------
__global__ __launch_bounds__(256, 2)
void hgemm_qkv(const __half* __restrict__ A,
               float* __restrict__ Cq, float* __restrict__ Ck,
               float* __restrict__ Cv)
{
    extern __shared__ uint32_t smu[];
    const uint32_t smemU = smem_u32(smu);
    const int K = 2048;

    const int tid  = threadIdx.x;
    const int lane = tid & 31;
    const int w    = tid >> 5;
    const int wm   = (w & 1) * 64;
    const int wn   = (w >> 1) * 32;
    const int rA   = lane >> 2;
    const int kq   = lane & 3;
    const int m0   = blockIdx.y * 128;
    const int bnG  = blockIdx.x * 128;

    const __half* Bsrc;
    float* C;
    int ldc, bn;
    if (bnG < 2048)      { Bsrc = g_qwT; C = Cq; ldc = 2048; bn = bnG; }
    else if (bnG < 2560) { Bsrc = g_kwT; C = Ck; ldc = 512;  bn = bnG - 2048; }
    else                 { Bsrc = g_vwT; C = Cv; ldc = 512;  bn = bnG - 2560; }

    const __half* arp[2];
    const __half* brp[2];
    uint32_t aoff[2], boff[2];
    #pragma unroll
    for (int i = 0; i < 2; i++) {
        int idx = tid + i * 256;
        int r = idx >> 2, cc = idx & 3;
        arp[i]  = A + (size_t)(m0 + r) * K + cc * 8;
        aoff[i] = 80u * (uint32_t)r + 16u * (uint32_t)cc;
        brp[i]  = Bsrc + (size_t)(bn + r) * K + cc * 8;
        boff[i] = 10240u + 80u * (uint32_t)r + 16u * (uint32_t)cc;
    }

    float c[4][4][4] = {};
    H_PIPELINE();

    #pragma unroll
    for (int mt = 0; mt < 4; mt++) {
        #pragma unroll
        for (int h = 0; h < 2; h++) {
            int r = wm + mt * 16 + rA + h * 8;
            float* dst = C + (size_t)(m0 + r) * ldc + bn;
            #pragma unroll
            for (int nt = 0; nt < 4; nt++) {
                int col = wn + nt * 8 + (kq << 1);
                dst[col]     = c[mt][nt][h * 2 + 0];
                dst[col + 1] = c[mt][nt][h * 2 + 1];
            }
        }
    }
}

// ----------------------------------------------------------------------------
// Fast transpose + fp32->fp16: src[R][C] f32 -> dst[C][R] f16.
// 64-row x 128-col tiles: 8 independent float4 loads/thread (latency hiding),
// 64B-contiguous per-lane half stores.  blockIdx.z = expert.
// ----------------------------------------------------------------------------
__global__ __launch_bounds__(256) void convT128(
    const float* __restrict__ src, __half* __restrict__ dst, int R, int C)
{
    __shared__ float s[64][132];
    const size_t eo = (size_t)blockIdx.z * (size_t)R * (size_t)C;
    src += eo; dst += eo;
    const int c0 = blockIdx.x * 128, r0 = blockIdx.y * 64;
    const int c4 = threadIdx.x & 31, rr = threadIdx.x >> 5;
    #pragma unroll
    for (int b = 0; b < 8; b++) {
        int r = rr + b * 8;
        float4 v = *(const float4*)(src + (size_t)(r0 + r) * C + c0 + c4 * 4);
        s[r][c4*4+0] = v.x; s[r][c4*4+1] = v.y;
        s[r][c4*4+2] = v.z; s[r][c4*4+3] = v.w;
    }
    __syncthreads();
    const int c = threadIdx.x >> 1, hs = threadIdx.x & 1;
    __half* dcol = dst + (size_t)(c0 + c) * R + r0 + hs * 32;
    #pragma unroll
    for (int m = 0; m < 8; m++) {
        int rb = hs * 32 + m * 4;
        uint2 u;
        u.x = pkh(s[rb+0][c], s[rb+1][c]);
        u.y = pkh(s[rb+2][c], s[rb+3][c]);
        *(uint2*)(dcol + m * 4) = u;
    }
}

// ----------------------------------------------------------------------------
// fp16 mma flash attention.  Block = (q-tile 128, head). 256 thr, 8 warps.
// ----------------------------------------------------------------------------
#define ATTN_SMEM ((8704 + 2*4352 + 2*4608)*4)

#define AISSUE(S, KB) do {                                                     \
    const int kk0_ = (KB)*64;                                                  \
    uint32_t kb_ = smemU + (uint32_t)(8704 + (S)*4352)*4u;                     \
    uint32_t vb_ = smemU + (uint32_t)(17408 + (S)*4608)*4u;                    \
    _Pragma("unroll")                                                          \
    for (int i_=0;i_<4;i_++) {                                                 \
        int idx_ = tid + i_*256;                                               \
        int r_ = idx_>>4, c_ = idx_&15;                                        \
        cp16(kb_ + (uint32_t)(r_*68 + c_*4)*4u,                                \
             Kh + (size_t)(kk0_+r_)*KVH + kvh*HEAD + c_*8);                    \
        int d_ = idx_>>3, cv_ = idx_&7;                                        \
        cp16(vb_ + (uint32_t)(d_*36 + cv_*4)*4u,                               \
             Vt + (size_t)(kvh*HEAD + d_)*T_TOK + kk0_ + cv_*8);               \
    }                                                                          \
    asm volatile("cp.async.commit_group;" ::: "memory");                       \
} while(0)

__global__ __launch_bounds__(256) void attn_f16(
    const __half* __restrict__ Qh, const __half* __restrict__ Kh,
    const __half* __restrict__ Vt, __half* __restrict__ O)
{
    extern __shared__ uint32_t smw[];
    const uint32_t smemU = smem_u32(smw);
    const uint32_t* Qs = smw;                 // [128][68]

    const int h = blockIdx.y, kvh = h >> 2;
    const int qb = (int)gridDim.x - 1 - (int)blockIdx.x;
    const int q0 = qb * 128;
    const int tid = threadIdx.x, lane = tid & 31, w = tid >> 5;
    const int wr0 = w * 16;
    const int rA = lane >> 2;
    const int kq = lane & 3;
    const float scale = 0.08838834764831845f;

    #pragma unroll
    for (int i = 0; i < 8; i++) {
        int idx = tid + i * 256;
        int r = idx >> 4, c = idx & 15;
        cp16(smemU + (uint32_t)(r * 68 + c * 4) * 4u,
             Qh + (size_t)(q0 + r) * QH + h * HEAD + c * 8);
    }
    AISSUE(0, 0);

    float mA = -1e30f, mB = -1e30f, lA = 0.f, lB = 0.f;
    float of[16][4];
    #pragma unroll
    for (int i = 0; i < 16; i++)
        { of[i][0] = 0.f; of[i][1] = 0.f; of[i][2] = 0.f; of[i][3] = 0.f; }

    const int nkb = 2 * qb + 2;
    for (int kb = 0; kb < nkb; kb++) {
        const int k0 = kb * 64;
        asm volatile("cp.async.wait_group 0;" ::: "memory");
        __syncthreads();
        if (kb + 1 < nkb) AISSUE((kb + 1) & 1, kb + 1);

        const uint32_t* KsP = smw + 8704 + (kb & 1) * 4352;
        const uint32_t* VsP = smw + 17408 + (kb & 1) * 4608;

        if (q0 + wr0 + 15 >= k0) {
            float sf[8][4];
            #pragma unroll
            for (int nt = 0; nt < 8; nt++)
                { sf[nt][0]=0.f; sf[nt][1]=0.f; sf[nt][2]=0.f; sf[nt][3]=0.f; }
            #pragma unroll
            for (int ks = 0; ks < 8; ks++) {
                uint32_t aa[4];
                aa[0] = Qs[(wr0 + rA)     * 68 + ks * 8 + kq];
                aa[1] = Qs[(wr0 + rA + 8) * 68 + ks * 8 + kq];
                aa[2] = Qs[(wr0 + rA)     * 68 + ks * 8 + 4 + kq];
                aa[3] = Qs[(wr0 + rA + 8) * 68 + ks * 8 + 4 + kq];
                #pragma unroll
                for (int nt = 0; nt < 8; nt++) {
                    uint32_t bb[2];
                    bb[0] = KsP[(nt * 8 + rA) * 68 + ks * 8 + kq];
                    bb[1] = KsP[(nt * 8 + rA) * 68 + ks * 8 + 4 + kq];
                    MMA_F16(sf[nt], aa, bb);
                }
            }
            #pragma unroll
            for (int nt = 0; nt < 8; nt++) {
                sf[nt][0] *= scale; sf[nt][1] *= scale;
                sf[nt][2] *= scale; sf[nt][3] *= scale;
            }

            const int rowA = q0 + wr0 + rA;
            const int rowB = rowA + 8;
            if (kb >= 2 * qb) {
                #pragma unroll
                for (int nt = 0; nt < 8; nt++) {
                    #pragma unroll
                    for (int u = 0; u < 2; u++) {
                        int col = k0 + nt * 8 + kq * 2 + u;
                        if (col > rowA) sf[nt][u]     = -1e30f;
                        if (col > rowB) sf[nt][2 + u] = -1e30f;
                    }
                }
            }
            float mxA = -1e30f, mxB = -1e30f;
            #pragma unroll
            for (int nt = 0; nt < 8; nt++) {
                mxA = fmaxf(mxA, fmaxf(sf[nt][0], sf[nt][1]));
                mxB = fmaxf(mxB, fmaxf(sf[nt][2], sf[nt][3]));
            }
            mxA = fmaxf(mxA, __shfl_xor_sync(0xffffffffu, mxA, 1));
            mxA = fmaxf(mxA, __shfl_xor_sync(0xffffffffu, mxA, 2));
            mxB = fmaxf(mxB, __shfl_xor_sync(0xffffffffu, mxB, 1));
            mxB = fmaxf(mxB, __shfl_xor_sync(0xffffffffu, mxB, 2));
            float mnA = fmaxf(mA, mxA), mnB = fmaxf(mB, mxB);
            float cA = __expf(mA - mnA), cB = __expf(mB - mnB);
            mA = mnA; mB = mnB;
            float rsA = 0.f, rsB = 0.f;
            #pragma unroll
            for (int nt = 0; nt < 8; nt++) {
                sf[nt][0] = __expf(sf[nt][0] - mnA);
                sf[nt][1] = __expf(sf[nt][1] - mnA);
                sf[nt][2] = __expf(sf[nt][2] - mnB);
                sf[nt][3] = __expf(sf[nt][3] - mnB);
                rsA += sf[nt][0] + sf[nt][1];
                rsB += sf[nt][2] + sf[nt][3];
            }
            rsA += __shfl_xor_sync(0xffffffffu, rsA, 1);
            rsA += __shfl_xor_sync(0xffffffffu, rsA, 2);
            rsB += __shfl_xor_sync(0xffffffffu, rsB, 1);
            rsB += __shfl_xor_sync(0xffffffffu, rsB, 2);
            lA = lA * cA + rsA; lB = lB * cB + rsB;
            #pragma unroll
            for (int nt2 = 0; nt2 < 16; nt2++) {
                of[nt2][0] *= cA; of[nt2][1] *= cA;
                of[nt2][2] *= cB; of[nt2][3] *= cB;
            }

            const int src = rA * 4 + kq;
            #pragma unroll
            for (int ks = 0; ks < 4; ks++) {
                float s0 = __shfl_sync(0xffffffffu, sf[2*ks][0],   src);
                float s1 = __shfl_sync(0xffffffffu, sf[2*ks][1],   src);
                float s2 = __shfl_sync(0xffffffffu, sf[2*ks][2],   src);
                float s3 = __shfl_sync(0xffffffffu, sf[2*ks][3],   src);
                float s4 = __shfl_sync(0xffffffffu, sf[2*ks+1][0], src);
                float s5 = __shfl_sync(0xffffffffu, sf[2*ks+1][1], src);
                float s6 = __shfl_sync(0xffffffffu, sf[2*ks+1][2], src);
                float s7 = __shfl_sync(0xffffffffu, sf[2*ks+1][3], src);
                uint32_t aa[4];
                aa[0] = pkh(s0, s1);
                aa[1] = pkh(s2, s3);
                aa[2] = pkh(s4, s5);
                aa[3] = pkh(s6, s7);
                #pragma unroll
                for (int nt2 = 0; nt2 < 16; nt2++) {
                    int n = nt2 * 8 + rA;
                    uint32_t bb[2];
                    bb[0] = VsP[n * 36 + ks * 8 + kq];
                    bb[1] = VsP[n * 36 + ks * 8 + 4 + kq];
                    MMA_F16(of[nt2], aa, bb);
                }
            }
        }
    }

    const float iA = 1.f / lA, iB = 1.f / lB;
    const int rowA = q0 + wr0 + rA, rowB = rowA + 8;
    #pragma unroll
    for (int nt2 = 0; nt2 < 16; nt2++) {
        int col = h * HEAD + nt2 * 8 + kq * 2;
        *(__half2*)&O[(size_t)rowA * QH + col] =
            __floats2half2_rn(of[nt2][0] * iA, of[nt2][1] * iA);
        *(__half2*)&O[(size_t)rowB * QH + col] =
            __floats2half2_rn(of[nt2][2] * iB, of[nt2][3] * iB);
    }
}

// ----------------------------------------------------------------------------
// RMSNorm over D=2048 -> fp16 (+ optional fp32)
// ----------------------------------------------------------------------------
__global__ __launch_bounds__(256) void rmsnorm_h(
    const float* __restrict__ x, const float* __restrict__ w,
    __half* __restrict__ outh, float* __restrict__ out32)
{
    const int t = blockIdx.x, tid = threadIdx.x;
    const float4* xr = (const float4*)(x + (size_t)t*D_MODEL);
    float4 a = xr[tid], b = xr[tid+256];
    float ss = a.x*a.x + a.y*a.y + a.z*a.z + a.w*a.w
             + b.x*b.x + b.y*b.y + b.z*b.z + b.w*b.w;
    #pragma unroll
    for (int off=16; off>0; off>>=1) ss += __shfl_xor_sync(0xffffffffu, ss, off);
    __shared__ float red[8];
    if ((tid&31)==0) red[tid>>5] = ss;
    __syncthreads();
    float tot = red[0]+red[1]+red[2]+red[3]+red[4]+red[5]+red[6]+red[7];
    float inv = rsqrtf(tot/(float)D_MODEL + EPS);
    const float4* wr = (const float4*)w;
    float4 wa = wr[tid], wb = wr[tid+256];
    float4 va = make_float4(a.x*inv*wa.x, a.y*inv*wa.y, a.z*inv*wa.z, a.w*inv*wa.w);
    float4 vb = make_float4(b.x*inv*wb.x, b.y*inv*wb.y, b.z*inv*wb.z, b.w*inv*wb.w);
    __half2* oh = (__half2*)(outh + (size_t)t*D_MODEL);
    oh[tid*2]         = __floats2half2_rn(va.x, va.y);
    oh[tid*2+1]       = __floats2half2_rn(va.z, va.w);
    oh[(tid+256)*2]   = __floats2half2_rn(vb.x, vb.y);
    oh[(tid+256)*2+1] = __floats2half2_rn(vb.z, vb.w);
    if (out32) {
        float4* o32 = (float4*)(out32 + (size_t)t*D_MODEL);
        o32[tid]     = va;
        o32[tid+256] = vb;
    }
}

// ----------------------------------------------------------------------------
// Per-head RMSNorm + RoPE, fp32 in -> fp16 out
// ----------------------------------------------------------------------------
__global__ __launch_bounds__(128) void qknorm_rope_h(
    const float* __restrict__ x, __half* __restrict__ xo,
    const float* __restrict__ nw,
    const float* __restrict__ cosb, const float* __restrict__ sinb, int NH)
{
    const int row = blockIdx.x;
    const int t = row / NH;
    const int tid = threadIdx.x;
    float v = x[(size_t)row*HEAD + tid];
    float ss = v*v;
    #pragma unroll
    for (int off=16; off>0; off>>=1) ss += __shfl_xor_sync(0xffffffffu, ss, off);
    __shared__ float red[4];
    __shared__ float xs[HEAD];
    if ((tid&31)==0) red[tid>>5] = ss;
    __syncthreads();
    float tot = red[0]+red[1]+red[2]+red[3];
    float inv = rsqrtf(tot/(float)HEAD + EPS);
    float xn = v*inv*nw[tid];
    xs[tid] = xn;
    __syncthreads();
    float other = xs[tid^64];
    float c = cosb[(size_t)t*HEAD + tid];
    float s = sinb[(size_t)t*HEAD + tid];
    float outv = (tid < 64) ? (xn*c - other*s) : (xn*c + other*s);
    xo[(size_t)row*HEAD + tid] = __float2half(outv);
}

// ----------------------------------------------------------------------------
// MoE router (fp32 h2 for exact top-k)
// ----------------------------------------------------------------------------
__global__ __launch_bounds__(128) void router_kernel(
    const float* __restrict__ h2, const float* __restrict__ gw)
{
    const int t = blockIdx.x, tid = threadIdx.x;
    const int e = tid & 15, c = tid >> 4;
    const float* x = h2 + (size_t)t*D_MODEL;
    float acc = 0.f;
    for (int d = c*256; d < c*256+256; d++)
        acc += x[d]*gw[d*N_EXP + e];
    __shared__ float part[8][16];
    part[c][e] = acc;
    __syncthreads();
    if (tid == 0) {
        float lg[16];
        for (int ee=0; ee<16; ee++) {
            float s = 0.f;
            for (int cc=0; cc<8; cc++) s += part[cc][ee];
            lg[ee] = s;
        }
        float mx = lg[0];
        for (int ee=1; ee<16; ee++) mx = fmaxf(mx, lg[ee]);
        float pb[16]; float sum = 0.f;
        for (int ee=0; ee<16; ee++) { pb[ee] = expf(lg[ee]-mx); sum += pb[ee]; }
        float isum = 1.f/sum;
        for (int ee=0; ee<16; ee++) pb[ee] *= isum;
        bool used[16] = {};
        int idx4[4]; float w4[4]; float wsum = 0.f;
        for (int s4=0; s4<4; s4++) {
            int bi = -1; float bv = -1.f;
            for (int ee=0; ee<16; ee++)
                if (!used[ee] && pb[ee] > bv) { bv = pb[ee]; bi = ee; }
            used[bi] = true; idx4[s4] = bi; w4[s4] = bv; wsum += bv;
        }
        for (int s4=0; s4<4; s4++) {
            g_topidx[t*4+s4] = idx4[s4];
            g_topw[t*4+s4]   = w4[s4]/wsum;
            atomicAdd(&g_cnt[idx4[s4]], 1);
        }
    }
}

__global__ void zero_kernel() {
    if (threadIdx.x < N_EXP) g_cnt[threadIdx.x] = 0;
}
__global__ void offsets_kernel() {
    if (threadIdx.x == 0) {
        int acc = 0;
        for (int e=0; e<N_EXP; e++) { g_off[e] = acc; acc += g_cnt[e]; g_cursor[e] = 0; }
        g_off[N_EXP] = acc;
    }
}
__global__ __launch_bounds__(256) void scatter_kernel() {
    int idx = blockIdx.x*blockDim.x + threadIdx.x;
    if (idx >= SLOTS) return;
    int t = idx >> 2;
    int e = g_topidx[idx];
    int p = atomicAdd(&g_cursor[e], 1);
    int r = g_off[e] + p;
    g_tokperm[r] = t;
    g_slotrow[idx] = r;
}

// combine: out = resid2 + sum topw * downo_h[slotrow]  (fp16 expert outputs)
__global__ __launch_bounds__(256) void combine_kernel(float* __restrict__ out)
{
    int idx = blockIdx.x*blockDim.x + threadIdx.x;
    if (idx >= T_TOK*512) return;
    int t = idx >> 9, d4 = idx & 511;
    float4 acc = ((const float4*)(g_resid2 + (size_t)t*2048))[d4];
    #pragma unroll
    for (int s=0; s<4; s++) {
        int row = g_slotrow[t*4+s];
        float wgt = g_topw[t*4+s];
        const __half2* vp = (const __half2*)(g_downo_h + (size_t)row*2048) + d4*2;
        float2 va = __half22float2(vp[0]);
        float2 vb = __half22float2(vp[1]);
        acc.x += wgt*va.x; acc.y += wgt*va.y;
        acc.z += wgt*vb.x; acc.w += wgt*vb.y;
    }
    ((float4*)out)[idx] = acc;
}

// ----------------------------------------------------------------------------
// Launcher
// ----------------------------------------------------------------------------
extern "C" void kernel_launch(void* const* d_in, const int* in_sizes, int n_in,
                              void* d_out, int out_size)
{
    const float* hidden = (const float*)d_in[0];
    const float* cosb   = (const float*)d_in[1];
    const float* sinb   = (const float*)d_in[2];
    // d_in[3] attention_mask: exactly causal; applied analytically in-kernel
    const float* iln    = (const float*)d_in[4];
    const float* pln    = (const float*)d_in[5];
    const float* qw     = (const float*)d_in[6];
    const float* kw     = (const float*)d_in[7];
    const float* vw     = (const float*)d_in[8];
    const float* ow     = (const float*)d_in[9];
    const float* qnw    = (const float*)d_in[10];
    const float* knw    = (const float*)d_in[11];
    const float* gw     = (const float*)d_in[12];
    const float* guw    = (const float*)d_in[13];
    const float* dww    = (const float*)d_in[14];
    float* out = (float*)d_out;

    cudaFuncSetAttribute(attn_f16,  cudaFuncAttributeMaxDynamicSharedMemorySize, ATTN_SMEM);
    cudaFuncSetAttribute(hgemm_qkv, cudaFuncAttributeMaxDynamicSharedMemorySize, HGEMM_SMEM);
    cudaFuncSetAttribute((const void*)hgemm<0,2048>, cudaFuncAttributeMaxDynamicSharedMemorySize, HGEMM_SMEM);
    cudaFuncSetAttribute((const void*)hgemm<1,2048>, cudaFuncAttributeMaxDynamicSharedMemorySize, HGEMM_SMEM);
    cudaFuncSetAttribute((const void*)hgemm<2,1024>, cudaFuncAttributeMaxDynamicSharedMemorySize, HGEMM_SMEM);

    void* p;
    cudaGetSymbolAddress(&p, g_hnorm_h); __half* hnorm_h = (__half*)p;
    cudaGetSymbolAddress(&p, g_q);       float*  qbuf    = (float*)p;
    cudaGetSymbolAddress(&p, g_k);       float*  kbuf    = (float*)p;
    cudaGetSymbolAddress(&p, g_v);       float*  vbuf    = (float*)p;
    cudaGetSymbolAddress(&p, g_kh);      __half* khbuf   = (__half*)p;
    cudaGetSymbolAddress(&p, g_vT);      __half* vTbuf   = (__half*)p;
    cudaGetSymbolAddress(&p, g_attn_h);  __half* abuf_h  = (__half*)p;
    cudaGetSymbolAddress(&p, g_resid2);  float*  resid2  = (float*)p;
    cudaGetSymbolAddress(&p, g_h2);      float*  h2buf   = (float*)p;
    cudaGetSymbolAddress(&p, g_h2h);     __half* h2h     = (__half*)p;
    cudaGetSymbolAddress(&p, g_gated_h); __half* gth     = (__half*)p;
    cudaGetSymbolAddress(&p, g_downo_h); __half* dohbuf  = (__half*)p;
    cudaGetSymbolAddress(&p, g_qwT);     __half* qwT     = (__half*)p;
    cudaGetSymbolAddress(&p, g_kwT);     __half* kwT     = (__half*)p;
    cudaGetSymbolAddress(&p, g_vwT);     __half* vwT     = (__half*)p;
    cudaGetSymbolAddress(&p, g_owT);     __half* owT     = (__half*)p;
    cudaGetSymbolAddress(&p, g_guwT);    __half* guwT    = (__half*)p;
    cudaGetSymbolAddress(&p, g_dwwT);    __half* dwwT    = (__half*)p;

    // 0) weight transpose + fp16 conversion (high-MLP path)
    convT128<<<dim3(16, 32, 1),  256>>>(qw,  qwT,  2048, 2048);
    convT128<<<dim3(4,  32, 1),  256>>>(kw,  kwT,  2048, 512);
    convT128<<<dim3(4,  32, 1),  256>>>(vw,  vwT,  2048, 512);
    convT128<<<dim3(16, 32, 1),  256>>>(ow,  owT,  2048, 2048);
    convT128<<<dim3(16, 32, 16), 256>>>(guw, guwT, 2048, 2048);
    convT128<<<dim3(16, 16, 16), 256>>>(dww, dwwT, 1024, 2048);

    // 1) input RMSNorm -> fp16
    rmsnorm_h<<<T_TOK, 256>>>(hidden, iln, hnorm_h, nullptr);
    // 2) fused QKV projection (fp16 mma) -> fp32 q,k,v
    hgemm_qkv<<<dim3(24, T_TOK/128), 256, HGEMM_SMEM>>>(hnorm_h, qbuf, kbuf, vbuf);
    // 3) per-head norm + RoPE -> fp16 (Qh reuses hnorm_h buffer)
    qknorm_rope_h<<<T_TOK*N_Q,  128>>>(qbuf, hnorm_h, qnw, cosb, sinb, N_Q);
    qknorm_rope_h<<<T_TOK*N_KV, 128>>>(kbuf, khbuf, knw, cosb, sinb, N_KV);
    // 3b) V fp32 [T][512] -> fp16 transposed [512][T]
    convT128<<<dim3(4, 32, 1), 256>>>(vbuf, vTbuf, 2048, 512);
    // 4) causal GQA attention (fp16 mma) -> fp16 attn out
    attn_f16<<<dim3(T_TOK/128, N_Q), 256, ATTN_SMEM>>>(hnorm_h, khbuf, vTbuf, abuf_h);
    // 5) O projection + residual add (fp16 mma, fp32 out)
    hgemm<0,2048><<<dim3(D_MODEL/128, T_TOK/128), 256, HGEMM_SMEM>>>(abuf_h, owT, hidden, resid2, D_MODEL);
    // 6) post RMSNorm -> fp16 (+ fp32 for router)
    rmsnorm_h<<<T_TOK, 256>>>(resid2, pln, h2h, h2buf);
    // 7) MoE routing + expert permutation
    zero_kernel<<<1, 32>>>();
    router_kernel<<<T_TOK, 128>>>(h2buf, gw);
    offsets_kernel<<<1, 1>>>();
    scatter_kernel<<<SLOTS/256, 256>>>();
    // 8) sparse expert GEMMs (fp16 mma): gate_up+silu fused -> g_gated; down -> fp16
    hgemm<1,2048><<<dim3(F_FF/64, T_TOK/128, N_EXP), 256, HGEMM_SMEM>>>(h2h, guwT, nullptr, gth, F_FF);
    hgemm<2,1024><<<dim3(D_MODEL/128, T_TOK/128, N_EXP), 256, HGEMM_SMEM>>>(gth, dwwT, nullptr, dohbuf, 2048);
    // 9) weighted combine + residual
    combine_kernel<<<(T_TOK*512)/256, 256>>>(out);
}

// round 17
// speedup vs baseline: 1.0777x; 1.0777x over previous
#include <cuda_runtime.h>
#include <cuda_bf16.h>
#include <cuda_fp16.h>
#include <math.h>
#include <stdint.h>
#include <string.h>

// ----------------------------------------------------------------------------
// Problem constants
// ----------------------------------------------------------------------------
#define T_TOK 2048
#define D_MODEL 2048
#define N_Q 16
#define N_KV 4
#define HEAD 128
#define QH (N_Q*HEAD)      // 2048
#define KVH (N_KV*HEAD)    // 512
#define N_EXP 16
#define F_FF 1024
#define TOPK 4
#define SLOTS (T_TOK*TOPK) // 8192
#define EPS 1e-6f

// ----------------------------------------------------------------------------
// Scratch (device globals; no dynamic allocation allowed)
// ----------------------------------------------------------------------------
__device__ __half g_hnorm_h[T_TOK*D_MODEL];   // reused as Qh after QKV GEMM
__device__ float  g_q[T_TOK*QH];
__device__ float  g_k[T_TOK*KVH];
__device__ float  g_v[T_TOK*KVH];
__device__ __half g_kh[T_TOK*KVH];
__device__ __half g_vT[(size_t)KVH*T_TOK];    // [kvh*128+d][t] fp16
__device__ __half g_attn_h[T_TOK*QH];
__device__ float  g_resid2[T_TOK*D_MODEL];
__device__ float  g_h2[T_TOK*D_MODEL];
__device__ __half g_h2h[T_TOK*D_MODEL];
__device__ float  g_topw[SLOTS];
__device__ int    g_topidx[SLOTS];
__device__ int    g_cnt[N_EXP];
__device__ int    g_off[N_EXP+1];
__device__ int    g_cursor[N_EXP];
__device__ int    g_tokperm[SLOTS];
__device__ int    g_slotrow[SLOTS];
__device__ __half g_gated_h[(size_t)SLOTS*F_FF];
__device__ __half g_downo_h[(size_t)SLOTS*D_MODEL];
// fp16 transposed weights [N][K]
__device__ __half g_qwT[(size_t)2048*2048];
__device__ __half g_kwT[(size_t)512*2048];
__device__ __half g_vwT[(size_t)512*2048];
__device__ __half g_owT[(size_t)2048*2048];
__device__ __half g_guwT[(size_t)N_EXP*2048*2048];
__device__ __half g_dwwT[(size_t)N_EXP*2048*1024];

// ----------------------------------------------------------------------------
// helpers (baseline PTX; compute_103-safe, no 'a'-features)
// ----------------------------------------------------------------------------
__device__ __forceinline__ uint32_t smem_u32(const void* p) {
    uint32_t a;
    asm("{ .reg .u64 t; cvta.to.shared.u64 t, %1; cvt.u32.u64 %0, t; }"
        : "=r"(a) : "l"(p));
    return a;
}
__device__ __forceinline__ void cp16(uint32_t dst, const void* src) {
    asm volatile("cp.async.cg.shared.global [%0], [%1], 16;" :: "r"(dst), "l"(src));
}
__device__ __forceinline__ uint32_t pkh(float lo, float hi) {
    __half2 h = __floats2half2_rn(lo, hi);
    uint32_t u; memcpy(&u, &h, 4); return u;
}

#define MMA_F16(cc, aa, bb) \
    asm volatile("mma.sync.aligned.m16n8k16.row.col.f32.f16.f16.f32 " \
        "{%0,%1,%2,%3}, {%4,%5,%6,%7}, {%8,%9}, {%0,%1,%2,%3};" \
        : "+f"(cc[0]), "+f"(cc[1]), "+f"(cc[2]), "+f"(cc[3]) \
        : "r"(aa[0]), "r"(aa[1]), "r"(aa[2]), "r"(aa[3]), "r"(bb[0]), "r"(bb[1]))

// ----------------------------------------------------------------------------
// fp16 tensor-core GEMM: block 128x128x32(k halfs), 256 thr, 8 warps,
// 3-stage cp.async.  Stage = 20480B; 3 stages -> 2 CTA/SM.
// ----------------------------------------------------------------------------
#define HSTG_BYTES 20480u
#define HSTG_U32   5120
#define HGEMM_SMEM (3*20480)

#define H_ISSUE(S, IT) do {                                                    \
    const int k0_ = (IT)*32;                                                   \
    uint32_t sb_ = smemU + (uint32_t)(S)*HSTG_BYTES;                           \
    cp16(sb_ + aoff[0], arp[0] + k0_);                                         \
    cp16(sb_ + aoff[1], arp[1] + k0_);                                         \
    cp16(sb_ + boff[0], brp[0] + k0_);                                         \
    cp16(sb_ + boff[1], brp[1] + k0_);                                         \
    asm volatile("cp.async.commit_group;" ::: "memory");                       \
} while(0)

#define H_COMPUTE(S) do {                                                      \
    const uint32_t* as_ = smu + (S)*HSTG_U32;                                  \
    const uint32_t* bs_ = as_ + 2560;                                          \
    _Pragma("unroll")                                                          \
    for (int ks_ = 0; ks_ < 2; ks_++) {                                        \
        const int kk0 = ks_*8;                                                 \
        uint32_t af[4][4], bf[4][2];                                           \
        _Pragma("unroll")                                                      \
        for (int mt_=0; mt_<4; mt_++) {                                        \
            int r_ = wm + mt_*16 + rA;                                         \
            af[mt_][0] = as_[r_*20     + kk0 + kq];                            \
            af[mt_][1] = as_[(r_+8)*20 + kk0 + kq];                            \
            af[mt_][2] = as_[r_*20     + kk0 + 4 + kq];                        \
            af[mt_][3] = as_[(r_+8)*20 + kk0 + 4 + kq];                        \
        }                                                                      \
        _Pragma("unroll")                                                      \
        for (int nt_=0; nt_<4; nt_++) {                                        \
            int n_ = wn + nt_*8 + rA;                                          \
            bf[nt_][0] = bs_[n_*20 + kk0 + kq];                                \
            bf[nt_][1] = bs_[n_*20 + kk0 + 4 + kq];                            \
        }                                                                      \
        _Pragma("unroll")                                                      \
        for (int mt_=0; mt_<4; mt_++)                                          \
            _Pragma("unroll")                                                  \
            for (int nt_=0; nt_<4; nt_++)                                      \
                MMA_F16(c[mt_][nt_], af[mt_], bf[nt_]);                        \
    }                                                                          \
} while(0)

#define H_BODY(S) do {                                                         \
    asm volatile("cp.async.wait_group 1;" ::: "memory");                       \
    __syncthreads();                                                           \
    if (itv + 2 < nIter) { H_ISSUE(((S)+2)%3, itv+2); }                        \
    else { asm volatile("cp.async.commit_group;" ::: "memory"); }              \
    H_COMPUTE(S);                                                              \
    itv++;                                                                     \
} while(0)

#define H_PIPELINE()                                                           \
    const int nIter = K / 32;                                                  \
    H_ISSUE(0, 0);                                                             \
    H_ISSUE(1, 1);                                                             \
    int itv = 0;                                                               \
    while (itv + 3 <= nIter) { H_BODY(0); H_BODY(1); H_BODY(2); }              \
    if (itv < nIter) { H_BODY(0); }                                            \
    if (itv < nIter) { H_BODY(1); }

// MODE 0: plain (+Cadd, f32 out).
// MODE 1: MoE gate_up, N-tile = 64 gate cols + 64 up cols, fused silu -> half.
// MODE 2: MoE down -> half out.
template<int MODE, int K>
__global__ __launch_bounds__(256, 2)
void hgemm(const __half* __restrict__ A, const __half* __restrict__ Bt,
           const float* __restrict__ Cadd, void* __restrict__ Cv_, int ldc)
{
    extern __shared__ uint32_t smu[];
    const uint32_t smemU = smem_u32(smu);

    const int tid  = threadIdx.x;
    const int lane = tid & 31;
    const int w    = tid >> 5;
    const int wm   = (w & 1) * 64;
    const int wnh  = w >> 1;
    const int wn   = wnh * 32;
    const int rA   = lane >> 2;
    const int kq   = lane & 3;
    const int bn   = blockIdx.x * 128;     // MODE 0/2
    const int bn64 = blockIdx.x * 64;      // MODE 1 gate-col base
    const int m0   = blockIdx.y * 128;

    int cnt_rows = 128;
    int base = 0;
    size_t cBase;
    const __half* Bsrc = Bt;
    if (MODE == 0) {
        cBase = (size_t)m0 * ldc;
    } else {
        const int e = blockIdx.z;
        const int cnt = g_cnt[e];
        if (m0 >= cnt) return;
        base = g_off[e];
        cnt_rows = min(128, cnt - m0);
        Bsrc = Bt + (size_t)e * 2048u * (size_t)K;
        cBase = (size_t)(base + m0) * ldc;
    }

    const __half* arp[2];
    const __half* brp[2];
    uint32_t aoff[2], boff[2];
    #pragma unroll
    for (int i = 0; i < 2; i++) {
        int idx = tid + i * 256;
        int r = idx >> 2, cc = idx & 3;
        int rl = min(r, cnt_rows - 1);
        size_t gr;
        if (MODE == 0)      gr = (size_t)(m0 + r);
        else if (MODE == 1) gr = (size_t)g_tokperm[base + m0 + rl];
        else                gr = (size_t)(base + m0 + rl);
        arp[i]  = A + gr * (size_t)K + cc * 8;
        aoff[i] = 80u * (uint32_t)r + 16u * (uint32_t)cc;
        int bcol;
        if (MODE == 1) bcol = (r < 64) ? (bn64 + r) : (1024 + bn64 + r - 64);
        else           bcol = bn + r;
        brp[i]  = Bsrc + (size_t)bcol * K + cc * 8;
        boff[i] = 10240u + 80u * (uint32_t)r + 16u * (uint32_t)cc;
    }

    float c[4][4][4] = {};
    H_PIPELINE();

    if (MODE == 1) {
        // fused silu(gate)*up epilogue; gate accums cross warps via stage smem
        __syncthreads();
        float* Gbuf = (float*)smu;             // [128][68] f32
        if (wnh < 2) {
            #pragma unroll
            for (int mt = 0; mt < 4; mt++)
                #pragma unroll
                for (int h = 0; h < 2; h++) {
                    int r = wm + mt * 16 + rA + h * 8;
                    #pragma unroll
                    for (int nt = 0; nt < 4; nt++) {
                        int cg = wn + nt * 8 + (kq << 1);
                        Gbuf[r * 68 + cg]     = c[mt][nt][h * 2 + 0];
                        Gbuf[r * 68 + cg + 1] = c[mt][nt][h * 2 + 1];
                    }
                }
        }
        __syncthreads();
        if (wnh >= 2) {
            __half* C = (__half*)Cv_;
            #pragma unroll
            for (int mt = 0; mt < 4; mt++)
                #pragma unroll
                for (int h = 0; h < 2; h++) {
                    int r = wm + mt * 16 + rA + h * 8;
                    if (r < cnt_rows) {
                        __half* dst = C + cBase + (size_t)r * ldc + bn64;
                        #pragma unroll
                        for (int nt = 0; nt < 4; nt++) {
                            int cu = (wn - 64) + nt * 8 + (kq << 1);
                            float g0 = Gbuf[r * 68 + cu];
                            float g1 = Gbuf[r * 68 + cu + 1];
                            float u0 = c[mt][nt][h * 2 + 0];
                            float u1 = c[mt][nt][h * 2 + 1];
                            float o0 = u0 * (g0 / (1.f + __expf(-g0)));
                            float o1 = u1 * (g1 / (1.f + __expf(-g1)));
                            *(uint32_t*)(dst + cu) = pkh(o0, o1);
                        }
                    }
                }
        }
        return;
    }

    if (MODE == 2) {
        __half* C = (__half*)Cv_;
        #pragma unroll
        for (int mt = 0; mt < 4; mt++) {
            #pragma unroll
            for (int h = 0; h < 2; h++) {
                int r = wm + mt * 16 + rA + h * 8;
                if (r < cnt_rows) {
                    __half* dst = C + cBase + (size_t)r * ldc + bn;
                    #pragma unroll
                    for (int nt = 0; nt < 4; nt++) {
                        int col = wn + nt * 8 + (kq << 1);
                        *(uint32_t*)(dst + col) =
                            pkh(c[mt][nt][h*2+0], c[mt][nt][h*2+1]);
                    }
                }
            }
        }
        return;
    }

    float* C = (float*)Cv_;
    #pragma unroll
    for (int mt = 0; mt < 4; mt++) {
        #pragma unroll
        for (int h = 0; h < 2; h++) {
            int r = wm + mt * 16 + rA + h * 8;
            if (r < cnt_rows) {
                float* dst = C + cBase + (size_t)r * ldc + bn;
                const float* ad = Cadd ? (Cadd + cBase + (size_t)r * ldc + bn)
                                       : (const float*)0;
                #pragma unroll
                for (int nt = 0; nt < 4; nt++) {
                    int col = wn + nt * 8 + (kq << 1);
                    float v0 = c[mt][nt][h * 2 + 0];
                    float v1 = c[mt][nt][h * 2 + 1];
                    if (ad) { v0 += ad[col]; v1 += ad[col + 1]; }
                    dst[col]     = v0;
                    dst[col + 1] = v1;
                }
            }
        }
    }
}

// ----------------------------------------------------------------------------
// Fused QKV fp16 GEMM
// ----------------------------------------------------------------------------
__global__ __launch_bounds__(256, 2)
void hgemm_qkv(const __half* __restrict__ A,
               float* __restrict__ Cq, float* __restrict__ Ck,
               float* __restrict__ Cv)
{
    extern __shared__ uint32_t smu[];
    const uint32_t smemU = smem_u32(smu);
    const int K = 2048;

    const int tid  = threadIdx.x;
    const int lane = tid & 31;
    const int w    = tid >> 5;
    const int wm   = (w & 1) * 64;
    const int wn   = (w >> 1) * 32;
    const int rA   = lane >> 2;
    const int kq   = lane & 3;
    const int m0   = blockIdx.y * 128;
    const int bnG  = blockIdx.x * 128;

    const __half* Bsrc;
    float* C;
    int ldc, bn;
    if (bnG < 2048)      { Bsrc = g_qwT; C = Cq; ldc = 2048; bn = bnG; }
    else if (bnG < 2560) { Bsrc = g_kwT; C = Ck; ldc = 512;  bn = bnG - 2048; }
    else                 { Bsrc = g_vwT; C = Cv; ldc = 512;  bn = bnG - 2560; }

    const __half* arp[2];
    const __half* brp[2];
    uint32_t aoff[2], boff[2];
    #pragma unroll
    for (int i = 0; i < 2; i++) {
        int idx = tid + i * 256;
        int r = idx >> 2, cc = idx & 3;
        arp[i]  = A + (size_t)(m0 + r) * K + cc * 8;
        aoff[i] = 80u * (uint32_t)r + 16u * (uint32_t)cc;
        brp[i]  = Bsrc + (size_t)(bn + r) * K + cc * 8;
        boff[i] = 10240u + 80u * (uint32_t)r + 16u * (uint32_t)cc;
    }

    float c[4][4][4] = {};
    H_PIPELINE();

    #pragma unroll
    for (int mt = 0; mt < 4; mt++) {
        #pragma unroll
        for (int h = 0; h < 2; h++) {
            int r = wm + mt * 16 + rA + h * 8;
            float* dst = C + (size_t)(m0 + r) * ldc + bn;
            #pragma unroll
            for (int nt = 0; nt < 4; nt++) {
                int col = wn + nt * 8 + (kq << 1);
                dst[col]     = c[mt][nt][h * 2 + 0];
                dst[col + 1] = c[mt][nt][h * 2 + 1];
            }
        }
    }
}

// ----------------------------------------------------------------------------
// Fast transpose + fp32->fp16 (R15 proven version): 64x64 tiles,
// float4 reads, 32B-contiguous uint2 half writes.  blockIdx.z = expert.
// ----------------------------------------------------------------------------
__global__ __launch_bounds__(256) void convT64(
    const float* __restrict__ src, __half* __restrict__ dst, int R, int C)
{
    __shared__ float s[64][65];
    const size_t eo = (size_t)blockIdx.z * (size_t)R * (size_t)C;
    src += eo; dst += eo;
    const int c0 = blockIdx.x * 64, r0 = blockIdx.y * 64;
    const int c4 = threadIdx.x & 15, rr = threadIdx.x >> 4;
    #pragma unroll
    for (int b = 0; b < 4; b++) {
        int r = rr + b * 16;
        float4 v = *(const float4*)(src + (size_t)(r0 + r) * C + c0 + c4 * 4);
        s[r][c4*4+0] = v.x; s[r][c4*4+1] = v.y;
        s[r][c4*4+2] = v.z; s[r][c4*4+3] = v.w;
    }
    __syncthreads();
    const int c = threadIdx.x >> 2, seg = threadIdx.x & 3;
    __half* dcol = dst + (size_t)(c0 + c) * R + r0 + seg * 16;
    #pragma unroll
    for (int m = 0; m < 4; m++) {
        int rb = seg * 16 + m * 4;
        uint2 u;
        u.x = pkh(s[rb+0][c], s[rb+1][c]);
        u.y = pkh(s[rb+2][c], s[rb+3][c]);
        *(uint2*)(dcol + m * 4) = u;
    }
}

// ----------------------------------------------------------------------------
// fp16 mma flash attention.  Block = (q-tile 128, head). 256 thr, 8 warps.
// ----------------------------------------------------------------------------
#define ATTN_SMEM ((8704 + 2*4352 + 2*4608)*4)

#define AISSUE(S, KB) do {                                                     \
    const int kk0_ = (KB)*64;                                                  \
    uint32_t kb_ = smemU + (uint32_t)(8704 + (S)*4352)*4u;                     \
    uint32_t vb_ = smemU + (uint32_t)(17408 + (S)*4608)*4u;                    \
    _Pragma("unroll")                                                          \
    for (int i_=0;i_<4;i_++) {                                                 \
        int idx_ = tid + i_*256;                                               \
        int r_ = idx_>>4, c_ = idx_&15;                                        \
        cp16(kb_ + (uint32_t)(r_*68 + c_*4)*4u,                                \
             Kh + (size_t)(kk0_+r_)*KVH + kvh*HEAD + c_*8);                    \
        int d_ = idx_>>3, cv_ = idx_&7;                                        \
        cp16(vb_ + (uint32_t)(d_*36 + cv_*4)*4u,                               \
             Vt + (size_t)(kvh*HEAD + d_)*T_TOK + kk0_ + cv_*8);               \
    }                                                                          \
    asm volatile("cp.async.commit_group;" ::: "memory");                       \
} while(0)

__global__ __launch_bounds__(256) void attn_f16(
    const __half* __restrict__ Qh, const __half* __restrict__ Kh,
    const __half* __restrict__ Vt, __half* __restrict__ O)
{
    extern __shared__ uint32_t smw[];
    const uint32_t smemU = smem_u32(smw);
    const uint32_t* Qs = smw;                 // [128][68]

    const int h = blockIdx.y, kvh = h >> 2;
    const int qb = (int)gridDim.x - 1 - (int)blockIdx.x;
    const int q0 = qb * 128;
    const int tid = threadIdx.x, lane = tid & 31, w = tid >> 5;
    const int wr0 = w * 16;
    const int rA = lane >> 2;
    const int kq = lane & 3;
    const float scale = 0.08838834764831845f;

    #pragma unroll
    for (int i = 0; i < 8; i++) {
        int idx = tid + i * 256;
        int r = idx >> 4, c = idx & 15;
        cp16(smemU + (uint32_t)(r * 68 + c * 4) * 4u,
             Qh + (size_t)(q0 + r) * QH + h * HEAD + c * 8);
    }
    AISSUE(0, 0);

    float mA = -1e30f, mB = -1e30f, lA = 0.f, lB = 0.f;
    float of[16][4];
    #pragma unroll
    for (int i = 0; i < 16; i++)
        { of[i][0] = 0.f; of[i][1] = 0.f; of[i][2] = 0.f; of[i][3] = 0.f; }

    const int nkb = 2 * qb + 2;
    for (int kb = 0; kb < nkb; kb++) {
        const int k0 = kb * 64;
        asm volatile("cp.async.wait_group 0;" ::: "memory");
        __syncthreads();
        if (kb + 1 < nkb) AISSUE((kb + 1) & 1, kb + 1);

        const uint32_t* KsP = smw + 8704 + (kb & 1) * 4352;
        const uint32_t* VsP = smw + 17408 + (kb & 1) * 4608;

        if (q0 + wr0 + 15 >= k0) {
            float sf[8][4];
            #pragma unroll
            for (int nt = 0; nt < 8; nt++)
                { sf[nt][0]=0.f; sf[nt][1]=0.f; sf[nt][2]=0.f; sf[nt][3]=0.f; }
            #pragma unroll
            for (int ks = 0; ks < 8; ks++) {
                uint32_t aa[4];
                aa[0] = Qs[(wr0 + rA)     * 68 + ks * 8 + kq];
                aa[1] = Qs[(wr0 + rA + 8) * 68 + ks * 8 + kq];
                aa[2] = Qs[(wr0 + rA)     * 68 + ks * 8 + 4 + kq];
                aa[3] = Qs[(wr0 + rA + 8) * 68 + ks * 8 + 4 + kq];
                #pragma unroll
                for (int nt = 0; nt < 8; nt++) {
                    uint32_t bb[2];
                    bb[0] = KsP[(nt * 8 + rA) * 68 + ks * 8 + kq];
                    bb[1] = KsP[(nt * 8 + rA) * 68 + ks * 8 + 4 + kq];
                    MMA_F16(sf[nt], aa, bb);
                }
            }
            #pragma unroll
            for (int nt = 0; nt < 8; nt++) {
                sf[nt][0] *= scale; sf[nt][1] *= scale;
                sf[nt][2] *= scale; sf[nt][3] *= scale;
            }

            const int rowA = q0 + wr0 + rA;
            const int rowB = rowA + 8;
            if (kb >= 2 * qb) {
                #pragma unroll
                for (int nt = 0; nt < 8; nt++) {
                    #pragma unroll
                    for (int u = 0; u < 2; u++) {
                        int col = k0 + nt * 8 + kq * 2 + u;
                        if (col > rowA) sf[nt][u]     = -1e30f;
                        if (col > rowB) sf[nt][2 + u] = -1e30f;
                    }
                }
            }
            float mxA = -1e30f, mxB = -1e30f;
            #pragma unroll
            for (int nt = 0; nt < 8; nt++) {
                mxA = fmaxf(mxA, fmaxf(sf[nt][0], sf[nt][1]));
                mxB = fmaxf(mxB, fmaxf(sf[nt][2], sf[nt][3]));
            }
            mxA = fmaxf(mxA, __shfl_xor_sync(0xffffffffu, mxA, 1));
            mxA = fmaxf(mxA, __shfl_xor_sync(0xffffffffu, mxA, 2));
            mxB = fmaxf(mxB, __shfl_xor_sync(0xffffffffu, mxB, 1));
            mxB = fmaxf(mxB, __shfl_xor_sync(0xffffffffu, mxB, 2));
            float mnA = fmaxf(mA, mxA), mnB = fmaxf(mB, mxB);
            float cA = __expf(mA - mnA), cB = __expf(mB - mnB);
            mA = mnA; mB = mnB;
            float rsA = 0.f, rsB = 0.f;
            #pragma unroll
            for (int nt = 0; nt < 8; nt++) {
                sf[nt][0] = __expf(sf[nt][0] - mnA);
                sf[nt][1] = __expf(sf[nt][1] - mnA);
                sf[nt][2] = __expf(sf[nt][2] - mnB);
                sf[nt][3] = __expf(sf[nt][3] - mnB);
                rsA += sf[nt][0] + sf[nt][1];
                rsB += sf[nt][2] + sf[nt][3];
            }
            rsA += __shfl_xor_sync(0xffffffffu, rsA, 1);
            rsA += __shfl_xor_sync(0xffffffffu, rsA, 2);
            rsB += __shfl_xor_sync(0xffffffffu, rsB, 1);
            rsB += __shfl_xor_sync(0xffffffffu, rsB, 2);
            lA = lA * cA + rsA; lB = lB * cB + rsB;
            #pragma unroll
            for (int nt2 = 0; nt2 < 16; nt2++) {
                of[nt2][0] *= cA; of[nt2][1] *= cA;
                of[nt2][2] *= cB; of[nt2][3] *= cB;
            }

            const int src = rA * 4 + kq;
            #pragma unroll
            for (int ks = 0; ks < 4; ks++) {
                float s0 = __shfl_sync(0xffffffffu, sf[2*ks][0],   src);
                float s1 = __shfl_sync(0xffffffffu, sf[2*ks][1],   src);
                float s2 = __shfl_sync(0xffffffffu, sf[2*ks][2],   src);
                float s3 = __shfl_sync(0xffffffffu, sf[2*ks][3],   src);
                float s4 = __shfl_sync(0xffffffffu, sf[2*ks+1][0], src);
                float s5 = __shfl_sync(0xffffffffu, sf[2*ks+1][1], src);
                float s6 = __shfl_sync(0xffffffffu, sf[2*ks+1][2], src);
                float s7 = __shfl_sync(0xffffffffu, sf[2*ks+1][3], src);
                uint32_t aa[4];
                aa[0] = pkh(s0, s1);
                aa[1] = pkh(s2, s3);
                aa[2] = pkh(s4, s5);
                aa[3] = pkh(s6, s7);
                #pragma unroll
                for (int nt2 = 0; nt2 < 16; nt2++) {
                    int n = nt2 * 8 + rA;
                    uint32_t bb[2];
                    bb[0] = VsP[n * 36 + ks * 8 + kq];
                    bb[1] = VsP[n * 36 + ks * 8 + 4 + kq];
                    MMA_F16(of[nt2], aa, bb);
                }
            }
        }
    }

    const float iA = 1.f / lA, iB = 1.f / lB;
    const int rowA = q0 + wr0 + rA, rowB = rowA + 8;
    #pragma unroll
    for (int nt2 = 0; nt2 < 16; nt2++) {
        int col = h * HEAD + nt2 * 8 + kq * 2;
        *(__half2*)&O[(size_t)rowA * QH + col] =
            __floats2half2_rn(of[nt2][0] * iA, of[nt2][1] * iA);
        *(__half2*)&O[(size_t)rowB * QH + col] =
            __floats2half2_rn(of[nt2][2] * iB, of[nt2][3] * iB);
    }
}

// ----------------------------------------------------------------------------
// RMSNorm over D=2048 -> fp16 (+ optional fp32)
// ----------------------------------------------------------------------------
__global__ __launch_bounds__(256) void rmsnorm_h(
    const float* __restrict__ x, const float* __restrict__ w,
    __half* __restrict__ outh, float* __restrict__ out32)
{
    const int t = blockIdx.x, tid = threadIdx.x;
    const float4* xr = (const float4*)(x + (size_t)t*D_MODEL);
    float4 a = xr[tid], b = xr[tid+256];
    float ss = a.x*a.x + a.y*a.y + a.z*a.z + a.w*a.w
             + b.x*b.x + b.y*b.y + b.z*b.z + b.w*b.w;
    #pragma unroll
    for (int off=16; off>0; off>>=1) ss += __shfl_xor_sync(0xffffffffu, ss, off);
    __shared__ float red[8];
    if ((tid&31)==0) red[tid>>5] = ss;
    __syncthreads();
    float tot = red[0]+red[1]+red[2]+red[3]+red[4]+red[5]+red[6]+red[7];
    float inv = rsqrtf(tot/(float)D_MODEL + EPS);
    const float4* wr = (const float4*)w;
    float4 wa = wr[tid], wb = wr[tid+256];
    float4 va = make_float4(a.x*inv*wa.x, a.y*inv*wa.y, a.z*inv*wa.z, a.w*inv*wa.w);
    float4 vb = make_float4(b.x*inv*wb.x, b.y*inv*wb.y, b.z*inv*wb.z, b.w*inv*wb.w);
    __half2* oh = (__half2*)(outh + (size_t)t*D_MODEL);
    oh[tid*2]         = __floats2half2_rn(va.x, va.y);
    oh[tid*2+1]       = __floats2half2_rn(va.z, va.w);
    oh[(tid+256)*2]   = __floats2half2_rn(vb.x, vb.y);
    oh[(tid+256)*2+1] = __floats2half2_rn(vb.z, vb.w);
    if (out32) {
        float4* o32 = (float4*)(out32 + (size_t)t*D_MODEL);
        o32[tid]     = va;
        o32[tid+256] = vb;
    }
}

// ----------------------------------------------------------------------------
// Per-head RMSNorm + RoPE, fp32 in -> fp16 out
// ----------------------------------------------------------------------------
__global__ __launch_bounds__(128) void qknorm_rope_h(
    const float* __restrict__ x, __half* __restrict__ xo,
    const float* __restrict__ nw,
    const float* __restrict__ cosb, const float* __restrict__ sinb, int NH)
{
    const int row = blockIdx.x;
    const int t = row / NH;
    const int tid = threadIdx.x;
    float v = x[(size_t)row*HEAD + tid];
    float ss = v*v;
    #pragma unroll
    for (int off=16; off>0; off>>=1) ss += __shfl_xor_sync(0xffffffffu, ss, off);
    __shared__ float red[4];
    __shared__ float xs[HEAD];
    if ((tid&31)==0) red[tid>>5] = ss;
    __syncthreads();
    float tot = red[0]+red[1]+red[2]+red[3];
    float inv = rsqrtf(tot/(float)HEAD + EPS);
    float xn = v*inv*nw[tid];
    xs[tid] = xn;
    __syncthreads();
    float other = xs[tid^64];
    float c = cosb[(size_t)t*HEAD + tid];
    float s = sinb[(size_t)t*HEAD + tid];
    float outv = (tid < 64) ? (xn*c - other*s) : (xn*c + other*s);
    xo[(size_t)row*HEAD + tid] = __float2half(outv);
}

// ----------------------------------------------------------------------------
// MoE router (fp32 h2 for exact top-k)
// ----------------------------------------------------------------------------
__global__ __launch_bounds__(128) void router_kernel(
    const float* __restrict__ h2, const float* __restrict__ gw)
{
    const int t = blockIdx.x, tid = threadIdx.x;
    const int e = tid & 15, c = tid >> 4;
    const float* x = h2 + (size_t)t*D_MODEL;
    float acc = 0.f;
    for (int d = c*256; d < c*256+256; d++)
        acc += x[d]*gw[d*N_EXP + e];
    __shared__ float part[8][16];
    part[c][e] = acc;
    __syncthreads();
    if (tid == 0) {
        float lg[16];
        for (int ee=0; ee<16; ee++) {
            float s = 0.f;
            for (int cc=0; cc<8; cc++) s += part[cc][ee];
            lg[ee] = s;
        }
        float mx = lg[0];
        for (int ee=1; ee<16; ee++) mx = fmaxf(mx, lg[ee]);
        float pb[16]; float sum = 0.f;
        for (int ee=0; ee<16; ee++) { pb[ee] = expf(lg[ee]-mx); sum += pb[ee]; }
        float isum = 1.f/sum;
        for (int ee=0; ee<16; ee++) pb[ee] *= isum;
        bool used[16] = {};
        int idx4[4]; float w4[4]; float wsum = 0.f;
        for (int s4=0; s4<4; s4++) {
            int bi = -1; float bv = -1.f;
            for (int ee=0; ee<16; ee++)
                if (!used[ee] && pb[ee] > bv) { bv = pb[ee]; bi = ee; }
            used[bi] = true; idx4[s4] = bi; w4[s4] = bv; wsum += bv;
        }
        for (int s4=0; s4<4; s4++) {
            g_topidx[t*4+s4] = idx4[s4];
            g_topw[t*4+s4]   = w4[s4]/wsum;
            atomicAdd(&g_cnt[idx4[s4]], 1);
        }
    }
}

__global__ void zero_kernel() {
    if (threadIdx.x < N_EXP) g_cnt[threadIdx.x] = 0;
}
__global__ void offsets_kernel() {
    if (threadIdx.x == 0) {
        int acc = 0;
        for (int e=0; e<N_EXP; e++) { g_off[e] = acc; acc += g_cnt[e]; g_cursor[e] = 0; }
        g_off[N_EXP] = acc;
    }
}
__global__ __launch_bounds__(256) void scatter_kernel() {
    int idx = blockIdx.x*blockDim.x + threadIdx.x;
    if (idx >= SLOTS) return;
    int t = idx >> 2;
    int e = g_topidx[idx];
    int p = atomicAdd(&g_cursor[e], 1);
    int r = g_off[e] + p;
    g_tokperm[r] = t;
    g_slotrow[idx] = r;
}

// combine: out = resid2 + sum topw * downo_h[slotrow]  (fp16 expert outputs)
__global__ __launch_bounds__(256) void combine_kernel(float* __restrict__ out)
{
    int idx = blockIdx.x*blockDim.x + threadIdx.x;
    if (idx >= T_TOK*512) return;
    int t = idx >> 9, d4 = idx & 511;
    float4 acc = ((const float4*)(g_resid2 + (size_t)t*2048))[d4];
    #pragma unroll
    for (int s=0; s<4; s++) {
        int row = g_slotrow[t*4+s];
        float wgt = g_topw[t*4+s];
        const __half2* vp = (const __half2*)(g_downo_h + (size_t)row*2048) + d4*2;
        float2 va = __half22float2(vp[0]);
        float2 vb = __half22float2(vp[1]);
        acc.x += wgt*va.x; acc.y += wgt*va.y;
        acc.z += wgt*vb.x; acc.w += wgt*vb.y;
    }
    ((float4*)out)[idx] = acc;
}

// ----------------------------------------------------------------------------
// Launcher
// ----------------------------------------------------------------------------
extern "C" void kernel_launch(void* const* d_in, const int* in_sizes, int n_in,
                              void* d_out, int out_size)
{
    const float* hidden = (const float*)d_in[0];
    const float* cosb   = (const float*)d_in[1];
    const float* sinb   = (const float*)d_in[2];
    // d_in[3] attention_mask: exactly causal; applied analytically in-kernel
    const float* iln    = (const float*)d_in[4];
    const float* pln    = (const float*)d_in[5];
    const float* qw     = (const float*)d_in[6];
    const float* kw     = (const float*)d_in[7];
    const float* vw     = (const float*)d_in[8];
    const float* ow     = (const float*)d_in[9];
    const float* qnw    = (const float*)d_in[10];
    const float* knw    = (const float*)d_in[11];
    const float* gw     = (const float*)d_in[12];
    const float* guw    = (const float*)d_in[13];
    const float* dww    = (const float*)d_in[14];
    float* out = (float*)d_out;

    cudaFuncSetAttribute(attn_f16,  cudaFuncAttributeMaxDynamicSharedMemorySize, ATTN_SMEM);
    cudaFuncSetAttribute(hgemm_qkv, cudaFuncAttributeMaxDynamicSharedMemorySize, HGEMM_SMEM);
    cudaFuncSetAttribute((const void*)hgemm<0,2048>, cudaFuncAttributeMaxDynamicSharedMemorySize, HGEMM_SMEM);
    cudaFuncSetAttribute((const void*)hgemm<1,2048>, cudaFuncAttributeMaxDynamicSharedMemorySize, HGEMM_SMEM);
    cudaFuncSetAttribute((const void*)hgemm<2,1024>, cudaFuncAttributeMaxDynamicSharedMemorySize, HGEMM_SMEM);

    void* p;
    cudaGetSymbolAddress(&p, g_hnorm_h); __half* hnorm_h = (__half*)p;
    cudaGetSymbolAddress(&p, g_q);       float*  qbuf    = (float*)p;
    cudaGetSymbolAddress(&p, g_k);       float*  kbuf    = (float*)p;
    cudaGetSymbolAddress(&p, g_v);       float*  vbuf    = (float*)p;
    cudaGetSymbolAddress(&p, g_kh);      __half* khbuf   = (__half*)p;
    cudaGetSymbolAddress(&p, g_vT);      __half* vTbuf   = (__half*)p;
    cudaGetSymbolAddress(&p, g_attn_h);  __half* abuf_h  = (__half*)p;
    cudaGetSymbolAddress(&p, g_resid2);  float*  resid2  = (float*)p;
    cudaGetSymbolAddress(&p, g_h2);      float*  h2buf   = (float*)p;
    cudaGetSymbolAddress(&p, g_h2h);     __half* h2h     = (__half*)p;
    cudaGetSymbolAddress(&p, g_gated_h); __half* gth     = (__half*)p;
    cudaGetSymbolAddress(&p, g_downo_h); __half* dohbuf  = (__half*)p;
    cudaGetSymbolAddress(&p, g_qwT);     __half* qwT     = (__half*)p;
    cudaGetSymbolAddress(&p, g_kwT);     __half* kwT     = (__half*)p;
    cudaGetSymbolAddress(&p, g_vwT);     __half* vwT     = (__half*)p;
    cudaGetSymbolAddress(&p, g_owT);     __half* owT     = (__half*)p;
    cudaGetSymbolAddress(&p, g_guwT);    __half* guwT    = (__half*)p;
    cudaGetSymbolAddress(&p, g_dwwT);    __half* dwwT    = (__half*)p;

    // 0) weight transpose + fp16 conversion (R15 proven convT64)
    convT64<<<dim3(32, 32, 1),  256>>>(qw,  qwT,  2048, 2048);
    convT64<<<dim3(8,  32, 1),  256>>>(kw,  kwT,  2048, 512);
    convT64<<<dim3(8,  32, 1),  256>>>(vw,  vwT,  2048, 512);
    convT64<<<dim3(32, 32, 1),  256>>>(ow,  owT,  2048, 2048);
    convT64<<<dim3(32, 32, 16), 256>>>(guw, guwT, 2048, 2048);
    convT64<<<dim3(32, 16, 16), 256>>>(dww, dwwT, 1024, 2048);

    // 1) input RMSNorm -> fp16
    rmsnorm_h<<<T_TOK, 256>>>(hidden, iln, hnorm_h, nullptr);
    // 2) fused QKV projection (fp16 mma) -> fp32 q,k,v
    hgemm_qkv<<<dim3(24, T_TOK/128), 256, HGEMM_SMEM>>>(hnorm_h, qbuf, kbuf, vbuf);
    // 3) per-head norm + RoPE -> fp16 (Qh reuses hnorm_h buffer)
    qknorm_rope_h<<<T_TOK*N_Q,  128>>>(qbuf, hnorm_h, qnw, cosb, sinb, N_Q);
    qknorm_rope_h<<<T_TOK*N_KV, 128>>>(kbuf, khbuf, knw, cosb, sinb, N_KV);
    // 3b) V fp32 [T][512] -> fp16 transposed [512][T]
    convT64<<<dim3(8, 32, 1), 256>>>(vbuf, vTbuf, 2048, 512);
    // 4) causal GQA attention (fp16 mma) -> fp16 attn out
    attn_f16<<<dim3(T_TOK/128, N_Q), 256, ATTN_SMEM>>>(hnorm_h, khbuf, vTbuf, abuf_h);
    // 5) O projection + residual add (fp16 mma, fp32 out)
    hgemm<0,2048><<<dim3(D_MODEL/128, T_TOK/128), 256, HGEMM_SMEM>>>(abuf_h, owT, hidden, resid2, D_MODEL);
    // 6) post RMSNorm -> fp16 (+ fp32 for router)
    rmsnorm_h<<<T_TOK, 256>>>(resid2, pln, h2h, h2buf);
    // 7) MoE routing + expert permutation
    zero_kernel<<<1, 32>>>();
    router_kernel<<<T_TOK, 128>>>(h2buf, gw);
    offsets_kernel<<<1, 1>>>();
    scatter_kernel<<<SLOTS/256, 256>>>();
    // 8) sparse expert GEMMs (fp16 mma): gate_up+silu fused -> g_gated; down -> fp16
    hgemm<1,2048><<<dim3(F_FF/64, T_TOK/128, N_EXP), 256, HGEMM_SMEM>>>(h2h, guwT, nullptr, gth, F_FF);
    hgemm<2,1024><<<dim3(D_MODEL/128, T_TOK/128, N_EXP), 256, HGEMM_SMEM>>>(gth, dwwT, nullptr, dohbuf, 2048);
    // 9) weighted combine + residual
    combine_kernel<<<(T_TOK*512)/256, 256>>>(out);
}